// round 1
// baseline (speedup 1.0000x reference)
#include <cuda_runtime.h>
#include <math.h>

#define NV 50000
#define NE 600000
#define NM 100000
#define IN_CH 256
#define HC 256
#define NH 8

// ---------------- scratch (device globals; no runtime allocation) ----------------
__device__ float g_X0[NV * HC];        // X @ W            51.2 MB
__device__ float g_Xe[NM * HC];        // hyperedge feats  102.4 MB
__device__ float g_cnt[NM];            // incidence counts
__device__ float g_alphae[NM * NH];    // per-edge attention logits
__device__ float g_alpha[NE * NH];     // per-incidence leaky-relu logits
__device__ float g_aexp[NE * NH];      // exp(alpha - max)
__device__ float g_amax[NV * NH];      // segment max per vertex
__device__ float g_asum[NV * NH];      // segment sum per vertex

// ---------------- init: zero / -inf fill everything that accumulates ----------------
__global__ void k_init(float* __restrict__ out) {
    int i = blockIdx.x * blockDim.x + threadIdx.x;   // grid covers NM*64 float4
    float4 z = make_float4(0.f, 0.f, 0.f, 0.f);
    if (i < NM * 64) ((float4*)g_Xe)[i] = z;
    if (i < NV * 64) ((float4*)out)[i] = z;
    if (i < NV * 2) {   // NV*8 floats = NV*2 float4
        ((float4*)g_asum)[i] = z;
        ((float4*)g_amax)[i] = make_float4(-INFINITY, -INFINITY, -INFINITY, -INFINITY);
    }
    if (i < NM / 4) ((float4*)g_cnt)[i] = z;
}

// ---------------- fp32 GEMM: g_X0[N,256] = X[N,256] @ W[256,256] ----------------
// 128x128 tile, BK=8, 256 threads, 8x8 accumulators per thread.
__global__ void k_gemm(const float* __restrict__ A, const float* __restrict__ B) {
    __shared__ float As[8][128];
    __shared__ float Bs[8][128];
    const int tid = threadIdx.x;
    const int tx = tid & 15;       // 0..15 -> col group
    const int ty = tid >> 4;       // 0..15 -> row group
    const int rowBase = blockIdx.y * 128;
    const int colBase = blockIdx.x * 128;

    const int aRow = tid >> 1;           // 0..127
    const int aK   = (tid & 1) * 4;      // 0 or 4
    const int bK   = tid >> 5;           // 0..7
    const int bCol = (tid & 31) * 4;     // 0..124

    float acc[8][8];
#pragma unroll
    for (int i = 0; i < 8; i++)
#pragma unroll
        for (int j = 0; j < 8; j++) acc[i][j] = 0.f;

    for (int k0 = 0; k0 < IN_CH; k0 += 8) {
        float4 av = make_float4(0.f, 0.f, 0.f, 0.f);
        int gr = rowBase + aRow;
        if (gr < NV) av = *(const float4*)&A[gr * IN_CH + k0 + aK];
        As[aK + 0][aRow] = av.x;
        As[aK + 1][aRow] = av.y;
        As[aK + 2][aRow] = av.z;
        As[aK + 3][aRow] = av.w;
        float4 bv = *(const float4*)&B[(k0 + bK) * HC + colBase + bCol];
        *(float4*)&Bs[bK][bCol] = bv;
        __syncthreads();

#pragma unroll
        for (int k = 0; k < 8; k++) {
            float a[8], b[8];
            float4 a0 = *(const float4*)&As[k][ty * 8];
            float4 a1 = *(const float4*)&As[k][ty * 8 + 4];
            a[0] = a0.x; a[1] = a0.y; a[2] = a0.z; a[3] = a0.w;
            a[4] = a1.x; a[5] = a1.y; a[6] = a1.z; a[7] = a1.w;
            float4 b0 = *(const float4*)&Bs[k][tx * 8];
            float4 b1 = *(const float4*)&Bs[k][tx * 8 + 4];
            b[0] = b0.x; b[1] = b0.y; b[2] = b0.z; b[3] = b0.w;
            b[4] = b1.x; b[5] = b1.y; b[6] = b1.z; b[7] = b1.w;
#pragma unroll
            for (int i = 0; i < 8; i++)
#pragma unroll
                for (int j = 0; j < 8; j++) acc[i][j] += a[i] * b[j];
        }
        __syncthreads();
    }

#pragma unroll
    for (int i = 0; i < 8; i++) {
        int gr = rowBase + ty * 8 + i;
        if (gr < NV) {
            float* cp = &g_X0[gr * HC + colBase + tx * 8];
            *(float4*)cp       = make_float4(acc[i][0], acc[i][1], acc[i][2], acc[i][3]);
            *(float4*)(cp + 4) = make_float4(acc[i][4], acc[i][5], acc[i][6], acc[i][7]);
        }
    }
}

// ---------------- incidence -> hyperedge accumulation ----------------
// one float4 (4 channels) per thread; E*64 threads total
__global__ void k_scatter_e(const int* __restrict__ vertex, const int* __restrict__ edges) {
    long long idx = (long long)blockIdx.x * blockDim.x + threadIdx.x;
    if (idx >= (long long)NE * 64) return;
    int e = (int)(idx >> 6);
    int q = (int)(idx & 63);
    int v = vertex[e];
    int ed = edges[e];
    float4 x = ((const float4*)g_X0)[(long long)v * 64 + q];
    float* dst = &g_Xe[(long long)ed * HC + q * 4];
    atomicAdd(dst + 0, x.x);
    atomicAdd(dst + 1, x.y);
    atomicAdd(dst + 2, x.z);
    atomicAdd(dst + 3, x.w);
    if (q == 0) atomicAdd(&g_cnt[ed], 1.0f);
}

// ---------------- finalize hyperedge feats (mean) + per-head logits ----------------
__global__ void k_edge_alpha(const float* __restrict__ att) {
    int m = blockIdx.x;
    int c = threadIdx.x;               // 0..255; warp == head
    float inv = 1.0f / fmaxf(g_cnt[m], 1.0f);
    float x = g_Xe[m * HC + c] * inv;
    g_Xe[m * HC + c] = x;
    float p = x * att[c];
#pragma unroll
    for (int off = 16; off > 0; off >>= 1) p += __shfl_down_sync(0xffffffffu, p, off);
    if ((c & 31) == 0) g_alphae[m * NH + (c >> 5)] = p;
}

// ---------------- float atomic max ----------------
__device__ __forceinline__ void atomicMaxF(float* addr, float v) {
    if (v >= 0.f) atomicMax((int*)addr, __float_as_int(v));
    else          atomicMin((unsigned int*)addr, __float_as_uint(v));
}

// ---------------- per-incidence logits (leaky relu) + segment max ----------------
__global__ void k_inc_max(const int* __restrict__ vertex, const int* __restrict__ edges) {
    int idx = blockIdx.x * blockDim.x + threadIdx.x;
    if (idx >= NE * NH) return;
    int e = idx >> 3, h = idx & 7;
    float a = g_alphae[edges[e] * NH + h];
    a = (a >= 0.f) ? a : 0.2f * a;
    g_alpha[idx] = a;
    atomicMaxF(&g_amax[vertex[e] * NH + h], a);
}

// ---------------- exp + segment sum ----------------
__global__ void k_inc_exp(const int* __restrict__ vertex) {
    int idx = blockIdx.x * blockDim.x + threadIdx.x;
    if (idx >= NE * NH) return;
    int e = idx >> 3, h = idx & 7;
    int v = vertex[e];
    float ex = expf(g_alpha[idx] - g_amax[v * NH + h]);
    g_aexp[idx] = ex;
    atomicAdd(&g_asum[v * NH + h], ex);
}

// ---------------- edge -> vertex weighted scatter ----------------
__global__ void k_scatter_v(const int* __restrict__ vertex, const int* __restrict__ edges,
                            float* __restrict__ out) {
    long long idx = (long long)blockIdx.x * blockDim.x + threadIdx.x;
    if (idx >= (long long)NE * 64) return;
    int e = (int)(idx >> 6);
    int q = (int)(idx & 63);
    int h = q >> 3;                   // 8 float4's per head
    int v = vertex[e];
    int ed = edges[e];
    float attn = g_aexp[e * NH + h] / (g_asum[v * NH + h] + 1e-16f);
    float4 x = ((const float4*)g_Xe)[(long long)ed * 64 + q];
    float* dst = &out[(long long)v * HC + q * 4];
    atomicAdd(dst + 0, x.x * attn);
    atomicAdd(dst + 1, x.y * attn);
    atomicAdd(dst + 2, x.z * attn);
    atomicAdd(dst + 3, x.w * attn);
}

// ---------------- exact GELU in place ----------------
__global__ void k_gelu(float* __restrict__ out) {
    int idx = blockIdx.x * blockDim.x + threadIdx.x;
    if (idx >= NV * 64) return;
    float4 x = ((float4*)out)[idx];
    x.x = 0.5f * x.x * (1.0f + erff(x.x * 0.70710678118654752f));
    x.y = 0.5f * x.y * (1.0f + erff(x.y * 0.70710678118654752f));
    x.z = 0.5f * x.z * (1.0f + erff(x.z * 0.70710678118654752f));
    x.w = 0.5f * x.w * (1.0f + erff(x.w * 0.70710678118654752f));
    ((float4*)out)[idx] = x;
}

extern "C" void kernel_launch(void* const* d_in, const int* in_sizes, int n_in,
                              void* d_out, int out_size) {
    const float* X      = (const float*)d_in[0];
    const float* W      = (const float*)d_in[1];
    const float* att    = (const float*)d_in[2];
    const int*   vertex = (const int*)d_in[3];
    const int*   edges  = (const int*)d_in[4];
    float* out = (float*)d_out;

    // init scratch + output
    {
        int total = NM * 64;                       // largest region (float4 count)
        k_init<<<(total + 255) / 256, 256>>>(out);
    }
    // GEMM
    {
        dim3 grid(HC / 128, (NV + 127) / 128);
        k_gemm<<<grid, 256>>>(X, W);
    }
    // incidence -> edge
    {
        long long total = (long long)NE * 64;
        k_scatter_e<<<(int)((total + 255) / 256), 256>>>(vertex, edges);
    }
    // edge mean + logits
    k_edge_alpha<<<NM, 256>>>(att);
    // per-incidence alpha + segment max
    k_inc_max<<<(NE * NH + 255) / 256, 256>>>(vertex, edges);
    // exp + segment sum
    k_inc_exp<<<(NE * NH + 255) / 256, 256>>>(vertex);
    // edge -> vertex
    {
        long long total = (long long)NE * 64;
        k_scatter_v<<<(int)((total + 255) / 256), 256>>>(vertex, edges, out);
    }
    // gelu
    k_gelu<<<(NV * 64 + 255) / 256, 256>>>(out);
}

// round 2
// speedup vs baseline: 1.7941x; 1.7941x over previous
#include <cuda_runtime.h>
#include <math.h>

#define NV 50000
#define NE 600000
#define NM 100000
#define IN_CH 256
#define HC 256
#define NH 8

// ---------------- scratch (device globals; no runtime allocation) ----------------
__device__ float g_X0[NV * HC];        // X @ W            51.2 MB
__device__ float g_Xe[NM * HC];        // hyperedge feat SUMS (mean deferred)
__device__ float g_cnt[NM];            // incidence counts
__device__ float g_inv[NM];            // 1/max(cnt,1)
__device__ float g_alphae[NM * NH];    // per-hyperedge attention logits
__device__ float g_alpha[NE * NH];     // per-incidence leaky-relu logits
__device__ float g_aexp[NE * NH];      // exp(alpha-max), later attn*inv_cnt
__device__ float g_amax[NV * NH];      // segment max per vertex
__device__ float g_asum[NV * NH];      // segment sum per vertex

// vectorized global float4 reduction (sm_90+)
__device__ __forceinline__ void redAdd4(float* p, float4 v) {
    asm volatile("red.global.add.v4.f32 [%0], {%1,%2,%3,%4};"
                 :: "l"(p), "f"(v.x), "f"(v.y), "f"(v.z), "f"(v.w) : "memory");
}

// ---------------- init ----------------
__global__ void k_init(float* __restrict__ out) {
    int i = blockIdx.x * blockDim.x + threadIdx.x;   // grid covers NM*64 float4
    float4 z = make_float4(0.f, 0.f, 0.f, 0.f);
    if (i < NM * 64) ((float4*)g_Xe)[i] = z;
    if (i < NV * 64) ((float4*)out)[i] = z;
    if (i < NV * 2) {
        ((float4*)g_asum)[i] = z;
        ((float4*)g_amax)[i] = make_float4(-INFINITY, -INFINITY, -INFINITY, -INFINITY);
    }
    if (i < NM / 4) ((float4*)g_cnt)[i] = z;
}

// ---------------- fp32 GEMM: g_X0 = X @ W (128x128 tile, BK=8) ----------------
__global__ void k_gemm(const float* __restrict__ A, const float* __restrict__ B) {
    __shared__ float As[8][128];
    __shared__ float Bs[8][128];
    const int tid = threadIdx.x;
    const int tx = tid & 15;
    const int ty = tid >> 4;
    const int rowBase = blockIdx.y * 128;
    const int colBase = blockIdx.x * 128;

    const int aRow = tid >> 1;
    const int aK   = (tid & 1) * 4;
    const int bK   = tid >> 5;
    const int bCol = (tid & 31) * 4;

    float acc[8][8];
#pragma unroll
    for (int i = 0; i < 8; i++)
#pragma unroll
        for (int j = 0; j < 8; j++) acc[i][j] = 0.f;

    for (int k0 = 0; k0 < IN_CH; k0 += 8) {
        float4 av = make_float4(0.f, 0.f, 0.f, 0.f);
        int gr = rowBase + aRow;
        if (gr < NV) av = *(const float4*)&A[gr * IN_CH + k0 + aK];
        As[aK + 0][aRow] = av.x;
        As[aK + 1][aRow] = av.y;
        As[aK + 2][aRow] = av.z;
        As[aK + 3][aRow] = av.w;
        float4 bv = *(const float4*)&B[(k0 + bK) * HC + colBase + bCol];
        *(float4*)&Bs[bK][bCol] = bv;
        __syncthreads();

#pragma unroll
        for (int k = 0; k < 8; k++) {
            float a[8], b[8];
            float4 a0 = *(const float4*)&As[k][ty * 8];
            float4 a1 = *(const float4*)&As[k][ty * 8 + 4];
            a[0] = a0.x; a[1] = a0.y; a[2] = a0.z; a[3] = a0.w;
            a[4] = a1.x; a[5] = a1.y; a[6] = a1.z; a[7] = a1.w;
            float4 b0 = *(const float4*)&Bs[k][tx * 8];
            float4 b1 = *(const float4*)&Bs[k][tx * 8 + 4];
            b[0] = b0.x; b[1] = b0.y; b[2] = b0.z; b[3] = b0.w;
            b[4] = b1.x; b[5] = b1.y; b[6] = b1.z; b[7] = b1.w;
#pragma unroll
            for (int i = 0; i < 8; i++)
#pragma unroll
                for (int j = 0; j < 8; j++) acc[i][j] += a[i] * b[j];
        }
        __syncthreads();
    }

#pragma unroll
    for (int i = 0; i < 8; i++) {
        int gr = rowBase + ty * 8 + i;
        if (gr < NV) {
            float* cp = &g_X0[gr * HC + colBase + tx * 8];
            *(float4*)cp       = make_float4(acc[i][0], acc[i][1], acc[i][2], acc[i][3]);
            *(float4*)(cp + 4) = make_float4(acc[i][4], acc[i][5], acc[i][6], acc[i][7]);
        }
    }
}

// ---------------- incidence -> hyperedge accumulation (vector RED) ----------------
__global__ void k_scatter_e(const int* __restrict__ vertex, const int* __restrict__ edges) {
    long long idx = (long long)blockIdx.x * blockDim.x + threadIdx.x;
    if (idx >= (long long)NE * 64) return;
    int e = (int)(idx >> 6);
    int q = (int)(idx & 63);
    int v = __ldg(&vertex[e]);
    int ed = __ldg(&edges[e]);
    float4 x = ((const float4*)g_X0)[(long long)v * 64 + q];
    redAdd4(&g_Xe[(long long)ed * HC + q * 4], x);
    if (q == 0) atomicAdd(&g_cnt[ed], 1.0f);
}

// ---------------- per-hyperedge logits: alpha_e = inv * dot(Xe_sum, att) ----------------
// one warp per hyperedge; lane l -> channels [8l, 8l+8) (head = l>>2)
__global__ void k_edge_alpha(const float* __restrict__ att) {
    int warp = (blockIdx.x * blockDim.x + threadIdx.x) >> 5;
    if (warp >= NM) return;
    int lane = threadIdx.x & 31;
    const float4* xe = (const float4*)&g_Xe[warp * HC];
    float4 a0 = xe[lane * 2], a1 = xe[lane * 2 + 1];
    const float4* at = (const float4*)att;
    float4 b0 = __ldg(&at[lane * 2]), b1 = __ldg(&at[lane * 2 + 1]);
    float p = a0.x * b0.x + a0.y * b0.y + a0.z * b0.z + a0.w * b0.w
            + a1.x * b1.x + a1.y * b1.y + a1.z * b1.z + a1.w * b1.w;
    p += __shfl_xor_sync(0xffffffffu, p, 1);
    p += __shfl_xor_sync(0xffffffffu, p, 2);
    float inv = 1.0f / fmaxf(g_cnt[warp], 1.0f);
    if ((lane & 3) == 0) g_alphae[warp * NH + (lane >> 2)] = p * inv;
    if (lane == 0) g_inv[warp] = inv;
}

__device__ __forceinline__ void atomicMaxF(float* addr, float v) {
    if (v >= 0.f) atomicMax((int*)addr, __float_as_int(v));
    else          atomicMin((unsigned int*)addr, __float_as_uint(v));
}

// ---------------- leaky relu per incidence + segment max (all 8 heads / thread) ----------------
__global__ void k_inc_max(const int* __restrict__ vertex, const int* __restrict__ edges) {
    int e = blockIdx.x * blockDim.x + threadIdx.x;
    if (e >= NE) return;
    int ed = __ldg(&edges[e]);
    int v  = __ldg(&vertex[e]);
    float4 a0 = ((const float4*)g_alphae)[ed * 2];
    float4 a1 = ((const float4*)g_alphae)[ed * 2 + 1];
    a0.x = a0.x >= 0.f ? a0.x : 0.2f * a0.x;
    a0.y = a0.y >= 0.f ? a0.y : 0.2f * a0.y;
    a0.z = a0.z >= 0.f ? a0.z : 0.2f * a0.z;
    a0.w = a0.w >= 0.f ? a0.w : 0.2f * a0.w;
    a1.x = a1.x >= 0.f ? a1.x : 0.2f * a1.x;
    a1.y = a1.y >= 0.f ? a1.y : 0.2f * a1.y;
    a1.z = a1.z >= 0.f ? a1.z : 0.2f * a1.z;
    a1.w = a1.w >= 0.f ? a1.w : 0.2f * a1.w;
    ((float4*)g_alpha)[e * 2]     = a0;
    ((float4*)g_alpha)[e * 2 + 1] = a1;
    float* am = &g_amax[v * NH];
    atomicMaxF(am + 0, a0.x); atomicMaxF(am + 1, a0.y);
    atomicMaxF(am + 2, a0.z); atomicMaxF(am + 3, a0.w);
    atomicMaxF(am + 4, a1.x); atomicMaxF(am + 5, a1.y);
    atomicMaxF(am + 6, a1.z); atomicMaxF(am + 7, a1.w);
}

// ---------------- exp + segment sum (vector RED) ----------------
__global__ void k_inc_exp(const int* __restrict__ vertex) {
    int e = blockIdx.x * blockDim.x + threadIdx.x;
    if (e >= NE) return;
    int v = __ldg(&vertex[e]);
    float4 a0 = ((const float4*)g_alpha)[e * 2];
    float4 a1 = ((const float4*)g_alpha)[e * 2 + 1];
    float4 m0 = ((const float4*)g_amax)[v * 2];
    float4 m1 = ((const float4*)g_amax)[v * 2 + 1];
    float4 e0 = make_float4(expf(a0.x - m0.x), expf(a0.y - m0.y),
                            expf(a0.z - m0.z), expf(a0.w - m0.w));
    float4 e1 = make_float4(expf(a1.x - m1.x), expf(a1.y - m1.y),
                            expf(a1.z - m1.z), expf(a1.w - m1.w));
    ((float4*)g_aexp)[e * 2]     = e0;
    ((float4*)g_aexp)[e * 2 + 1] = e1;
    redAdd4(&g_asum[v * NH], e0);
    redAdd4(&g_asum[v * NH + 4], e1);
}

// ---------------- finalize attn weight: attn * inv_cnt(edge), in place ----------------
__global__ void k_attn(const int* __restrict__ vertex, const int* __restrict__ edges) {
    int e = blockIdx.x * blockDim.x + threadIdx.x;
    if (e >= NE) return;
    int v  = __ldg(&vertex[e]);
    int ed = __ldg(&edges[e]);
    float inv = g_inv[ed];
    float4 x0 = ((const float4*)g_aexp)[e * 2];
    float4 x1 = ((const float4*)g_aexp)[e * 2 + 1];
    float4 s0 = ((const float4*)g_asum)[v * 2];
    float4 s1 = ((const float4*)g_asum)[v * 2 + 1];
    x0.x = x0.x / (s0.x + 1e-16f) * inv;
    x0.y = x0.y / (s0.y + 1e-16f) * inv;
    x0.z = x0.z / (s0.z + 1e-16f) * inv;
    x0.w = x0.w / (s0.w + 1e-16f) * inv;
    x1.x = x1.x / (s1.x + 1e-16f) * inv;
    x1.y = x1.y / (s1.y + 1e-16f) * inv;
    x1.z = x1.z / (s1.z + 1e-16f) * inv;
    x1.w = x1.w / (s1.w + 1e-16f) * inv;
    ((float4*)g_aexp)[e * 2]     = x0;
    ((float4*)g_aexp)[e * 2 + 1] = x1;
}

// ---------------- edge -> vertex weighted scatter (vector RED) ----------------
__global__ void k_scatter_v(const int* __restrict__ vertex, const int* __restrict__ edges,
                            float* __restrict__ out) {
    long long idx = (long long)blockIdx.x * blockDim.x + threadIdx.x;
    if (idx >= (long long)NE * 64) return;
    int e = (int)(idx >> 6);
    int q = (int)(idx & 63);
    int h = q >> 3;
    int v  = __ldg(&vertex[e]);
    int ed = __ldg(&edges[e]);
    float w = g_aexp[e * NH + h];            // attn * inv_cnt already folded
    float4 x = ((const float4*)g_Xe)[(long long)ed * 64 + q];
    x.x *= w; x.y *= w; x.z *= w; x.w *= w;
    redAdd4(&out[(long long)v * HC + q * 4], x);
}

// ---------------- exact GELU in place ----------------
__global__ void k_gelu(float* __restrict__ out) {
    int idx = blockIdx.x * blockDim.x + threadIdx.x;
    if (idx >= NV * 64) return;
    float4 x = ((float4*)out)[idx];
    x.x = 0.5f * x.x * (1.0f + erff(x.x * 0.70710678118654752f));
    x.y = 0.5f * x.y * (1.0f + erff(x.y * 0.70710678118654752f));
    x.z = 0.5f * x.z * (1.0f + erff(x.z * 0.70710678118654752f));
    x.w = 0.5f * x.w * (1.0f + erff(x.w * 0.70710678118654752f));
    ((float4*)out)[idx] = x;
}

extern "C" void kernel_launch(void* const* d_in, const int* in_sizes, int n_in,
                              void* d_out, int out_size) {
    const float* X      = (const float*)d_in[0];
    const float* W      = (const float*)d_in[1];
    const float* att    = (const float*)d_in[2];
    const int*   vertex = (const int*)d_in[3];
    const int*   edges  = (const int*)d_in[4];
    float* out = (float*)d_out;

    k_init<<<(NM * 64 + 255) / 256, 256>>>(out);
    {
        dim3 grid(HC / 128, (NV + 127) / 128);
        k_gemm<<<grid, 256>>>(X, W);
    }
    {
        long long total = (long long)NE * 64;
        k_scatter_e<<<(int)((total + 255) / 256), 256>>>(vertex, edges);
    }
    k_edge_alpha<<<(NM * 32 + 255) / 256, 256>>>(att);
    k_inc_max<<<(NE + 255) / 256, 256>>>(vertex, edges);
    k_inc_exp<<<(NE + 255) / 256, 256>>>(vertex);
    k_attn<<<(NE + 255) / 256, 256>>>(vertex, edges);
    {
        long long total = (long long)NE * 64;
        k_scatter_v<<<(int)((total + 255) / 256), 256>>>(vertex, edges, out);
    }
    k_gelu<<<(NV * 64 + 255) / 256, 256>>>(out);
}

// round 3
// speedup vs baseline: 2.0338x; 1.1336x over previous
#include <cuda_runtime.h>
#include <math.h>

#define NV 50000
#define NE 600000
#define NM 100000
#define IN_CH 256
#define HC 256
#define NH 8
#define MAXDEG 128   // smem-cached softmax path; general fallback beyond

// ---------------- scratch (device globals) ----------------
__device__ float g_X0[NV * HC];        // X @ W
__device__ float g_Xe[NM * HC];        // hyperedge feature SUMS (mean deferred)
__device__ float g_alphae[NM * NH];    // per-hyperedge logits (mean-scaled)
__device__ float g_inv[NM];            // 1/max(deg,1)
__device__ int   g_cntE[NM], g_cntV[NV];
__device__ int   g_startE[NM + 1], g_startV[NV + 1];
__device__ int   g_curE[NM], g_curV[NV];
__device__ int   g_incE[NE];           // per-hyperedge incidence list -> vertex ids
__device__ int   g_incV[NE];           // per-vertex incidence list  -> edge ids

// ---------------- init: zero histograms ----------------
__global__ void k_init() {
    int i = blockIdx.x * blockDim.x + threadIdx.x;
    if (i < NM) g_cntE[i] = 0;
    if (i < NV) g_cntV[i] = 0;
}

// ---------------- histogram ----------------
__global__ void k_hist(const int* __restrict__ vertex, const int* __restrict__ edges) {
    int e = blockIdx.x * blockDim.x + threadIdx.x;
    if (e >= NE) return;
    atomicAdd(&g_cntE[__ldg(&edges[e])], 1);
    atomicAdd(&g_cntV[__ldg(&vertex[e])], 1);
}

// ---------------- single-block exclusive scan (2 blocks: E and V) ----------------
__global__ void k_scan() {
    const int  n     = (blockIdx.x == 0) ? NM : NV;
    const int* cnt   = (blockIdx.x == 0) ? g_cntE : g_cntV;
    int*       start = (blockIdx.x == 0) ? g_startE : g_startV;
    int*       cur   = (blockIdx.x == 0) ? g_curE : g_curV;

    __shared__ int warpSums[32];
    const int per = (n + 1023) / 1024;
    const int base = threadIdx.x * per;
    int s = 0;
    for (int i = 0; i < per; i++) {
        int idx = base + i;
        if (idx < n) s += cnt[idx];
    }
    int lane = threadIdx.x & 31, wid = threadIdx.x >> 5;
    int v = s;
#pragma unroll
    for (int o = 1; o < 32; o <<= 1) {
        int t = __shfl_up_sync(0xffffffffu, v, o);
        if (lane >= o) v += t;
    }
    if (lane == 31) warpSums[wid] = v;
    __syncthreads();
    if (wid == 0) {
        int w = warpSums[lane];
#pragma unroll
        for (int o = 1; o < 32; o <<= 1) {
            int t = __shfl_up_sync(0xffffffffu, w, o);
            if (lane >= o) w += t;
        }
        warpSums[lane] = w;
    }
    __syncthreads();
    int excl = v - s + (wid > 0 ? warpSums[wid - 1] : 0);
    int run = excl;
    for (int i = 0; i < per; i++) {
        int idx = base + i;
        if (idx < n) {
            start[idx] = run;
            cur[idx] = run;
            run += cnt[idx];
        }
    }
    if (threadIdx.x == 0) start[n] = warpSums[31];
}

// ---------------- fill CSR incidence lists ----------------
__global__ void k_fill(const int* __restrict__ vertex, const int* __restrict__ edges) {
    int e = blockIdx.x * blockDim.x + threadIdx.x;
    if (e >= NE) return;
    int v  = __ldg(&vertex[e]);
    int ed = __ldg(&edges[e]);
    int pE = atomicAdd(&g_curE[ed], 1);
    g_incE[pE] = v;
    int pV = atomicAdd(&g_curV[v], 1);
    g_incV[pV] = ed;
}

// ---------------- fp32 GEMM: g_X0 = X @ W (128x128 tile, BK=8) ----------------
__global__ void k_gemm(const float* __restrict__ A, const float* __restrict__ B) {
    __shared__ float As[8][128];
    __shared__ float Bs[8][128];
    const int tid = threadIdx.x;
    const int tx = tid & 15;
    const int ty = tid >> 4;
    const int rowBase = blockIdx.y * 128;
    const int colBase = blockIdx.x * 128;

    const int aRow = tid >> 1;
    const int aK   = (tid & 1) * 4;
    const int bK   = tid >> 5;
    const int bCol = (tid & 31) * 4;

    float acc[8][8];
#pragma unroll
    for (int i = 0; i < 8; i++)
#pragma unroll
        for (int j = 0; j < 8; j++) acc[i][j] = 0.f;

    for (int k0 = 0; k0 < IN_CH; k0 += 8) {
        float4 av = make_float4(0.f, 0.f, 0.f, 0.f);
        int gr = rowBase + aRow;
        if (gr < NV) av = *(const float4*)&A[gr * IN_CH + k0 + aK];
        As[aK + 0][aRow] = av.x;
        As[aK + 1][aRow] = av.y;
        As[aK + 2][aRow] = av.z;
        As[aK + 3][aRow] = av.w;
        float4 bv = *(const float4*)&B[(k0 + bK) * HC + colBase + bCol];
        *(float4*)&Bs[bK][bCol] = bv;
        __syncthreads();

#pragma unroll
        for (int k = 0; k < 8; k++) {
            float a[8], b[8];
            float4 a0 = *(const float4*)&As[k][ty * 8];
            float4 a1 = *(const float4*)&As[k][ty * 8 + 4];
            a[0] = a0.x; a[1] = a0.y; a[2] = a0.z; a[3] = a0.w;
            a[4] = a1.x; a[5] = a1.y; a[6] = a1.z; a[7] = a1.w;
            float4 b0 = *(const float4*)&Bs[k][tx * 8];
            float4 b1 = *(const float4*)&Bs[k][tx * 8 + 4];
            b[0] = b0.x; b[1] = b0.y; b[2] = b0.z; b[3] = b0.w;
            b[4] = b1.x; b[5] = b1.y; b[6] = b1.z; b[7] = b1.w;
#pragma unroll
            for (int i = 0; i < 8; i++)
#pragma unroll
                for (int j = 0; j < 8; j++) acc[i][j] += a[i] * b[j];
        }
        __syncthreads();
    }

#pragma unroll
    for (int i = 0; i < 8; i++) {
        int gr = rowBase + ty * 8 + i;
        if (gr < NV) {
            float* cp = &g_X0[gr * HC + colBase + tx * 8];
            *(float4*)cp       = make_float4(acc[i][0], acc[i][1], acc[i][2], acc[i][3]);
            *(float4*)(cp + 4) = make_float4(acc[i][4], acc[i][5], acc[i][6], acc[i][7]);
        }
    }
}

// ---------------- per-hyperedge aggregate + logits (warp per hyperedge) ----------------
__global__ void k_edge_agg(const float* __restrict__ att) {
    int m = (blockIdx.x * blockDim.x + threadIdx.x) >> 5;
    if (m >= NM) return;
    int lane = threadIdx.x & 31;
    int s0 = g_startE[m], s1 = g_startE[m + 1];

    float4 acc0 = make_float4(0.f, 0.f, 0.f, 0.f);
    float4 acc1 = make_float4(0.f, 0.f, 0.f, 0.f);
    for (int i = s0; i < s1; i++) {
        int v = g_incE[i];
        const float4* xr = (const float4*)&g_X0[(size_t)v * HC];
        float4 x0 = xr[lane * 2], x1 = xr[lane * 2 + 1];
        acc0.x += x0.x; acc0.y += x0.y; acc0.z += x0.z; acc0.w += x0.w;
        acc1.x += x1.x; acc1.y += x1.y; acc1.z += x1.z; acc1.w += x1.w;
    }
    float4* xe = (float4*)&g_Xe[(size_t)m * HC];
    xe[lane * 2]     = acc0;
    xe[lane * 2 + 1] = acc1;

    const float4* at = (const float4*)att;
    float4 b0 = __ldg(&at[lane * 2]), b1 = __ldg(&at[lane * 2 + 1]);
    float p = acc0.x * b0.x + acc0.y * b0.y + acc0.z * b0.z + acc0.w * b0.w
            + acc1.x * b1.x + acc1.y * b1.y + acc1.z * b1.z + acc1.w * b1.w;
    p += __shfl_xor_sync(0xffffffffu, p, 1);
    p += __shfl_xor_sync(0xffffffffu, p, 2);
    float inv = 1.0f / fmaxf((float)(s1 - s0), 1.0f);
    if ((lane & 3) == 0) g_alphae[m * NH + (lane >> 2)] = p * inv;
    if (lane == 0) g_inv[m] = inv;
}

__device__ __forceinline__ float gelu1(float x) {
    return 0.5f * x * (1.0f + erff(x * 0.70710678118654752f));
}

// ---------------- fused per-vertex softmax + weighted gather + GELU ----------------
__global__ void k_vertex(float* __restrict__ out) {
    __shared__ float sx[8][MAXDEG * 8];   // per-warp exp cache
    int warp = (blockIdx.x * blockDim.x + threadIdx.x) >> 5;
    if (warp >= NV) return;
    int lane = threadIdx.x & 31;
    int wib = threadIdx.x >> 5;
    float* sex = sx[wib];

    int s0 = g_startV[warp], s1 = g_startV[warp + 1];
    int deg = s1 - s0;
    bool small = (deg <= MAXDEG);

    int h = lane & 7, islot = lane >> 3;

    // P1: per-head segment max (lanes with same h cooperate)
    float m = -INFINITY;
    for (int base = 0; base < deg; base += 4) {
        int i = base + islot;
        if (i < deg) {
            int ed = g_incV[s0 + i];
            float a = g_alphae[ed * NH + h];
            a = a >= 0.f ? a : 0.2f * a;
            m = fmaxf(m, a);
        }
    }
    m = fmaxf(m, __shfl_xor_sync(0xffffffffu, m, 8));
    m = fmaxf(m, __shfl_xor_sync(0xffffffffu, m, 16));

    // P2: exp + sum; cache exps in smem
    float s = 0.f;
    for (int base = 0; base < deg; base += 4) {
        int i = base + islot;
        if (i < deg) {
            int ed = g_incV[s0 + i];
            float a = g_alphae[ed * NH + h];
            a = a >= 0.f ? a : 0.2f * a;
            float ex = expf(a - m);
            s += ex;
            if (small) sex[i * 8 + h] = ex;
        }
    }
    s += __shfl_xor_sync(0xffffffffu, s, 8);
    s += __shfl_xor_sync(0xffffffffu, s, 16);
    __syncwarp();

    // P3: weighted gather; lane covers channels [lane*8, lane*8+8), head = lane>>2
    float m_t = __shfl_sync(0xffffffffu, m, lane >> 2);
    float s_t = __shfl_sync(0xffffffffu, s, lane >> 2);
    float rs = 1.0f / (s_t + 1e-16f);

    float4 acc0 = make_float4(0.f, 0.f, 0.f, 0.f);
    float4 acc1 = make_float4(0.f, 0.f, 0.f, 0.f);
    for (int i = 0; i < deg; i++) {
        int ed = g_incV[s0 + i];
        float w;
        if (small) {
            w = sex[i * 8 + (lane >> 2)] * rs * g_inv[ed];
        } else {
            float a = g_alphae[ed * NH + (lane >> 2)];
            a = a >= 0.f ? a : 0.2f * a;
            w = expf(a - m_t) * rs * g_inv[ed];
        }
        const float4* xr = (const float4*)&g_Xe[(size_t)ed * HC];
        float4 x0 = xr[lane * 2], x1 = xr[lane * 2 + 1];
        acc0.x += x0.x * w; acc0.y += x0.y * w; acc0.z += x0.z * w; acc0.w += x0.w * w;
        acc1.x += x1.x * w; acc1.y += x1.y * w; acc1.z += x1.z * w; acc1.w += x1.w * w;
    }

    acc0.x = gelu1(acc0.x); acc0.y = gelu1(acc0.y);
    acc0.z = gelu1(acc0.z); acc0.w = gelu1(acc0.w);
    acc1.x = gelu1(acc1.x); acc1.y = gelu1(acc1.y);
    acc1.z = gelu1(acc1.z); acc1.w = gelu1(acc1.w);

    float4* op = (float4*)&out[(size_t)warp * HC];
    op[lane * 2]     = acc0;
    op[lane * 2 + 1] = acc1;
}

extern "C" void kernel_launch(void* const* d_in, const int* in_sizes, int n_in,
                              void* d_out, int out_size) {
    const float* X      = (const float*)d_in[0];
    const float* W      = (const float*)d_in[1];
    const float* att    = (const float*)d_in[2];
    const int*   vertex = (const int*)d_in[3];
    const int*   edges  = (const int*)d_in[4];
    float* out = (float*)d_out;

    k_init<<<(NM + 255) / 256, 256>>>();
    k_hist<<<(NE + 255) / 256, 256>>>(vertex, edges);
    k_scan<<<2, 1024>>>();
    k_fill<<<(NE + 255) / 256, 256>>>(vertex, edges);
    {
        dim3 grid(HC / 128, (NV + 127) / 128);
        k_gemm<<<grid, 256>>>(X, W);
    }
    k_edge_agg<<<(NM * 32 + 255) / 256, 256>>>(att);
    k_vertex<<<(NV * 32 + 255) / 256, 256>>>(out);
}

// round 4
// speedup vs baseline: 2.2935x; 1.1277x over previous
#include <cuda_runtime.h>
#include <math.h>

#define NV 50000
#define NE 600000
#define NM 100000
#define IN_CH 256
#define HC 256
#define NH 8

// ---------------- scratch (device globals) ----------------
__device__ float g_X0[NV * HC];        // X @ W
__device__ float g_Xe[NM * HC];        // hyperedge feature MEANS
__device__ float g_alphae[NM * NH];    // per-hyperedge logits
__device__ int   g_cntE[NM], g_cntV[NV];
__device__ int   g_startE[NM + 1], g_startV[NV + 1];
__device__ int   g_curE[NM], g_curV[NV];
__device__ int   g_incE[NE];           // per-hyperedge incidence -> vertex ids
__device__ int   g_incV[NE];           // per-vertex incidence -> edge ids

// ---------------- init: zero histograms ----------------
__global__ void k_init() {
    int i = blockIdx.x * blockDim.x + threadIdx.x;
    if (i < NM) g_cntE[i] = 0;
    if (i < NV) g_cntV[i] = 0;
}

// ---------------- histogram ----------------
__global__ void k_hist(const int* __restrict__ vertex, const int* __restrict__ edges) {
    int e = blockIdx.x * blockDim.x + threadIdx.x;
    if (e >= NE) return;
    atomicAdd(&g_cntE[__ldg(&edges[e])], 1);
    atomicAdd(&g_cntV[__ldg(&vertex[e])], 1);
}

// ---------------- single-block exclusive scan (2 blocks: E and V) ----------------
__global__ void k_scan() {
    const int  n     = (blockIdx.x == 0) ? NM : NV;
    const int* cnt   = (blockIdx.x == 0) ? g_cntE : g_cntV;
    int*       start = (blockIdx.x == 0) ? g_startE : g_startV;
    int*       cur   = (blockIdx.x == 0) ? g_curE : g_curV;

    __shared__ int warpSums[32];
    const int per = (n + 1023) / 1024;
    const int base = threadIdx.x * per;
    int s = 0;
    for (int i = 0; i < per; i++) {
        int idx = base + i;
        if (idx < n) s += cnt[idx];
    }
    int lane = threadIdx.x & 31, wid = threadIdx.x >> 5;
    int v = s;
#pragma unroll
    for (int o = 1; o < 32; o <<= 1) {
        int t = __shfl_up_sync(0xffffffffu, v, o);
        if (lane >= o) v += t;
    }
    if (lane == 31) warpSums[wid] = v;
    __syncthreads();
    if (wid == 0) {
        int w = warpSums[lane];
#pragma unroll
        for (int o = 1; o < 32; o <<= 1) {
            int t = __shfl_up_sync(0xffffffffu, w, o);
            if (lane >= o) w += t;
        }
        warpSums[lane] = w;
    }
    __syncthreads();
    int excl = v - s + (wid > 0 ? warpSums[wid - 1] : 0);
    int run = excl;
    for (int i = 0; i < per; i++) {
        int idx = base + i;
        if (idx < n) {
            start[idx] = run;
            cur[idx] = run;
            run += cnt[idx];
        }
    }
    if (threadIdx.x == 0) start[n] = warpSums[31];
}

// ---------------- fill CSR incidence lists ----------------
__global__ void k_fill(const int* __restrict__ vertex, const int* __restrict__ edges) {
    int e = blockIdx.x * blockDim.x + threadIdx.x;
    if (e >= NE) return;
    int v  = __ldg(&vertex[e]);
    int ed = __ldg(&edges[e]);
    int pE = atomicAdd(&g_curE[ed], 1);
    g_incE[pE] = v;
    int pV = atomicAdd(&g_curV[v], 1);
    g_incV[pV] = ed;
}

// ---------------- fp32 GEMM: g_X0 = X @ W (128x128 tile, BK=8) ----------------
__global__ void k_gemm(const float* __restrict__ A, const float* __restrict__ B) {
    __shared__ float As[8][128];
    __shared__ float Bs[8][128];
    const int tid = threadIdx.x;
    const int tx = tid & 15;
    const int ty = tid >> 4;
    const int rowBase = blockIdx.y * 128;
    const int colBase = blockIdx.x * 128;

    const int aRow = tid >> 1;
    const int aK   = (tid & 1) * 4;
    const int bK   = tid >> 5;
    const int bCol = (tid & 31) * 4;

    float acc[8][8];
#pragma unroll
    for (int i = 0; i < 8; i++)
#pragma unroll
        for (int j = 0; j < 8; j++) acc[i][j] = 0.f;

    for (int k0 = 0; k0 < IN_CH; k0 += 8) {
        float4 av = make_float4(0.f, 0.f, 0.f, 0.f);
        int gr = rowBase + aRow;
        if (gr < NV) av = *(const float4*)&A[gr * IN_CH + k0 + aK];
        As[aK + 0][aRow] = av.x;
        As[aK + 1][aRow] = av.y;
        As[aK + 2][aRow] = av.z;
        As[aK + 3][aRow] = av.w;
        float4 bv = *(const float4*)&B[(k0 + bK) * HC + colBase + bCol];
        *(float4*)&Bs[bK][bCol] = bv;
        __syncthreads();

#pragma unroll
        for (int k = 0; k < 8; k++) {
            float a[8], b[8];
            float4 a0 = *(const float4*)&As[k][ty * 8];
            float4 a1 = *(const float4*)&As[k][ty * 8 + 4];
            a[0] = a0.x; a[1] = a0.y; a[2] = a0.z; a[3] = a0.w;
            a[4] = a1.x; a[5] = a1.y; a[6] = a1.z; a[7] = a1.w;
            float4 b0 = *(const float4*)&Bs[k][tx * 8];
            float4 b1 = *(const float4*)&Bs[k][tx * 8 + 4];
            b[0] = b0.x; b[1] = b0.y; b[2] = b0.z; b[3] = b0.w;
            b[4] = b1.x; b[5] = b1.y; b[6] = b1.z; b[7] = b1.w;
#pragma unroll
            for (int i = 0; i < 8; i++)
#pragma unroll
                for (int j = 0; j < 8; j++) acc[i][j] += a[i] * b[j];
        }
        __syncthreads();
    }

#pragma unroll
    for (int i = 0; i < 8; i++) {
        int gr = rowBase + ty * 8 + i;
        if (gr < NV) {
            float* cp = &g_X0[gr * HC + colBase + tx * 8];
            *(float4*)cp       = make_float4(acc[i][0], acc[i][1], acc[i][2], acc[i][3]);
            *(float4*)(cp + 4) = make_float4(acc[i][4], acc[i][5], acc[i][6], acc[i][7]);
        }
    }
}

#define ACC8(A0, A1, X0, X1, W0)                                            \
    A0.x += X0.x * W0; A0.y += X0.y * W0; A0.z += X0.z * W0; A0.w += X0.w * W0; \
    A1.x += X1.x * W0; A1.y += X1.y * W0; A1.z += X1.z * W0; A1.w += X1.w * W0;

// ---------------- per-hyperedge aggregate (mean) + logits (warp per hyperedge) ----------------
__global__ void k_edge_agg(const float* __restrict__ att) {
    int m = (blockIdx.x * blockDim.x + threadIdx.x) >> 5;
    if (m >= NM) return;
    int lane = threadIdx.x & 31;
    int s0 = g_startE[m], s1 = g_startE[m + 1];

    float4 acc0 = make_float4(0.f, 0.f, 0.f, 0.f);
    float4 acc1 = make_float4(0.f, 0.f, 0.f, 0.f);
    int i = s0;
    for (; i + 2 <= s1; i += 2) {
        int v0 = __ldg(&g_incE[i]);
        int v1 = __ldg(&g_incE[i + 1]);
        const float4* xr0 = (const float4*)&g_X0[(size_t)v0 * HC];
        const float4* xr1 = (const float4*)&g_X0[(size_t)v1 * HC];
        float4 xa0 = __ldg(&xr0[lane * 2]), xa1 = __ldg(&xr0[lane * 2 + 1]);
        float4 xb0 = __ldg(&xr1[lane * 2]), xb1 = __ldg(&xr1[lane * 2 + 1]);
        ACC8(acc0, acc1, xa0, xa1, 1.0f);
        ACC8(acc0, acc1, xb0, xb1, 1.0f);
    }
    if (i < s1) {
        int v0 = __ldg(&g_incE[i]);
        const float4* xr0 = (const float4*)&g_X0[(size_t)v0 * HC];
        float4 xa0 = __ldg(&xr0[lane * 2]), xa1 = __ldg(&xr0[lane * 2 + 1]);
        ACC8(acc0, acc1, xa0, xa1, 1.0f);
    }

    float inv = 1.0f / fmaxf((float)(s1 - s0), 1.0f);
    acc0.x *= inv; acc0.y *= inv; acc0.z *= inv; acc0.w *= inv;
    acc1.x *= inv; acc1.y *= inv; acc1.z *= inv; acc1.w *= inv;

    float4* xe = (float4*)&g_Xe[(size_t)m * HC];
    xe[lane * 2]     = acc0;
    xe[lane * 2 + 1] = acc1;

    const float4* at = (const float4*)att;
    float4 b0 = __ldg(&at[lane * 2]), b1 = __ldg(&at[lane * 2 + 1]);
    float p = acc0.x * b0.x + acc0.y * b0.y + acc0.z * b0.z + acc0.w * b0.w
            + acc1.x * b1.x + acc1.y * b1.y + acc1.z * b1.z + acc1.w * b1.w;
    p += __shfl_xor_sync(0xffffffffu, p, 1);
    p += __shfl_xor_sync(0xffffffffu, p, 2);
    if ((lane & 3) == 0) g_alphae[m * NH + (lane >> 2)] = p;
}

__device__ __forceinline__ float gelu1(float x) {
    return 0.5f * x * (1.0f + erff(x * 0.70710678118654752f));
}

// ---------------- fused per-vertex online-softmax + weighted gather + GELU ----------------
__global__ void k_vertex(float* __restrict__ out) {
    int warp = (blockIdx.x * blockDim.x + threadIdx.x) >> 5;
    if (warp >= NV) return;
    int lane = threadIdx.x & 31;

    int s0 = g_startV[warp], s1 = g_startV[warp + 1];
    int deg = s1 - s0;

    int h = lane & 7, islot = lane >> 3;

    // online (max, sum) over this lane's subset for head h
    float m = -INFINITY, s = 0.f;
    for (int i = islot; i < deg; i += 4) {
        int ed = __ldg(&g_incV[s0 + i]);
        float a = g_alphae[ed * NH + h];
        a = a >= 0.f ? a : 0.2f * a;
        float mn = fmaxf(m, a);
        s = s * __expf(m - mn) + __expf(a - mn);
        m = mn;
    }
    // combine across the 4 subsets per head (xor 8, 16)
#pragma unroll
    for (int off = 8; off <= 16; off <<= 1) {
        float m2 = __shfl_xor_sync(0xffffffffu, m, off);
        float s2 = __shfl_xor_sync(0xffffffffu, s, off);
        float mn = fmaxf(m, m2);
        float sn = 0.f;
        if (s  > 0.f) sn += s  * __expf(m  - mn);
        if (s2 > 0.f) sn += s2 * __expf(m2 - mn);
        m = mn; s = sn;
    }

    // redistribute: lane covers channels [lane*8, lane*8+8), head hh = lane>>2
    int hh = lane >> 2;
    float m_t = __shfl_sync(0xffffffffu, m, hh);
    float s_t = __shfl_sync(0xffffffffu, s, hh);
    float rs = 1.0f / (s_t + 1e-16f);

    float4 acc0 = make_float4(0.f, 0.f, 0.f, 0.f);
    float4 acc1 = make_float4(0.f, 0.f, 0.f, 0.f);
    int i = 0;
    for (; i + 2 <= deg; i += 2) {
        int e0 = __ldg(&g_incV[s0 + i]);
        int e1 = __ldg(&g_incV[s0 + i + 1]);
        float a0 = g_alphae[e0 * NH + hh];
        float a1 = g_alphae[e1 * NH + hh];
        const float4* xr0 = (const float4*)&g_Xe[(size_t)e0 * HC];
        const float4* xr1 = (const float4*)&g_Xe[(size_t)e1 * HC];
        float4 xa0 = __ldg(&xr0[lane * 2]), xa1 = __ldg(&xr0[lane * 2 + 1]);
        float4 xb0 = __ldg(&xr1[lane * 2]), xb1 = __ldg(&xr1[lane * 2 + 1]);
        a0 = a0 >= 0.f ? a0 : 0.2f * a0;
        a1 = a1 >= 0.f ? a1 : 0.2f * a1;
        float w0 = __expf(a0 - m_t) * rs;
        float w1 = __expf(a1 - m_t) * rs;
        ACC8(acc0, acc1, xa0, xa1, w0);
        ACC8(acc0, acc1, xb0, xb1, w1);
    }
    if (i < deg) {
        int e0 = __ldg(&g_incV[s0 + i]);
        float a0 = g_alphae[e0 * NH + hh];
        const float4* xr0 = (const float4*)&g_Xe[(size_t)e0 * HC];
        float4 xa0 = __ldg(&xr0[lane * 2]), xa1 = __ldg(&xr0[lane * 2 + 1]);
        a0 = a0 >= 0.f ? a0 : 0.2f * a0;
        float w0 = __expf(a0 - m_t) * rs;
        ACC8(acc0, acc1, xa0, xa1, w0);
    }

    acc0.x = gelu1(acc0.x); acc0.y = gelu1(acc0.y);
    acc0.z = gelu1(acc0.z); acc0.w = gelu1(acc0.w);
    acc1.x = gelu1(acc1.x); acc1.y = gelu1(acc1.y);
    acc1.z = gelu1(acc1.z); acc1.w = gelu1(acc1.w);

    float4* op = (float4*)&out[(size_t)warp * HC];
    op[lane * 2]     = acc0;
    op[lane * 2 + 1] = acc1;
}

extern "C" void kernel_launch(void* const* d_in, const int* in_sizes, int n_in,
                              void* d_out, int out_size) {
    const float* X      = (const float*)d_in[0];
    const float* W      = (const float*)d_in[1];
    const float* att    = (const float*)d_in[2];
    const int*   vertex = (const int*)d_in[3];
    const int*   edges  = (const int*)d_in[4];
    float* out = (float*)d_out;

    static cudaStream_t s2 = nullptr;
    static cudaEvent_t evFork = nullptr, evJoin = nullptr;
    if (s2 == nullptr) {
        cudaStreamCreate(&s2);
        cudaEventCreateWithFlags(&evFork, cudaEventDisableTiming);
        cudaEventCreateWithFlags(&evJoin, cudaEventDisableTiming);
    }

    // fork: GEMM on side stream, concurrent with CSR build on main stream
    cudaEventRecord(evFork, 0);
    cudaStreamWaitEvent(s2, evFork, 0);
    {
        dim3 grid(HC / 128, (NV + 127) / 128);
        k_gemm<<<grid, 256, 0, s2>>>(X, W);
    }
    k_init<<<(NM + 255) / 256, 256>>>();
    k_hist<<<(NE + 255) / 256, 256>>>(vertex, edges);
    k_scan<<<2, 1024>>>();
    k_fill<<<(NE + 255) / 256, 256>>>(vertex, edges);
    // join: edge aggregation needs both X0 (s2) and CSR (main)
    cudaEventRecord(evJoin, s2);
    cudaStreamWaitEvent(0, evJoin, 0);

    k_edge_agg<<<(NM * 32 + 255) / 256, 256>>>(att);
    k_vertex<<<(NV * 32 + 255) / 256, 256>>>(out);
}

// round 5
// speedup vs baseline: 3.3385x; 1.4556x over previous
#include <cuda_runtime.h>
#include <math.h>

#define NV 50000
#define NE 600000
#define NM 100000
#define IN_CH 256
#define HC 256
#define NH 8

#define SCAN_CHUNK 4096                       // elements per scan block (1024 thr * 4)
#define NBLK_E ((NM + SCAN_CHUNK - 1) / SCAN_CHUNK)   // 25
#define NBLK_V ((NV + SCAN_CHUNK - 1) / SCAN_CHUNK)   // 13

// ---------------- scratch (device globals) ----------------
__device__ float g_X0[NV * HC];        // X @ W
__device__ float g_Xe[NM * HC];        // hyperedge feature MEANS
__device__ float g_alphae[NM * NH];    // per-hyperedge logits
__device__ int   g_cntE[NM], g_cntV[NV];
__device__ int   g_startE[NM + 1], g_startV[NV + 1];
__device__ int   g_curE[NM], g_curV[NV];
__device__ int   g_incE[NE];           // per-hyperedge incidence -> vertex ids
__device__ int   g_incV[NE];           // per-vertex incidence -> edge ids
__device__ int   g_blkSumE[NBLK_E], g_blkSumV[NBLK_V];
__device__ int   g_blkOffE[NBLK_E], g_blkOffV[NBLK_V];

// ---------------- init: zero histograms ----------------
__global__ void k_init() {
    int i = blockIdx.x * blockDim.x + threadIdx.x;
    if (i < NM) g_cntE[i] = 0;
    if (i < NV) g_cntV[i] = 0;
}

// ---------------- histogram ----------------
__global__ void k_hist(const int* __restrict__ vertex, const int* __restrict__ edges) {
    int e = blockIdx.x * blockDim.x + threadIdx.x;
    if (e >= NE) return;
    atomicAdd(&g_cntE[__ldg(&edges[e])], 1);
    atomicAdd(&g_cntV[__ldg(&vertex[e])], 1);
}

// ---------------- scan phase A: per-block sums (coalesced int4) ----------------
__global__ void k_scanA() {
    bool isE = (blockIdx.x < NBLK_E);
    int lb = isE ? blockIdx.x : blockIdx.x - NBLK_E;
    int n = isE ? NM : NV;
    const int* cnt = isE ? g_cntE : g_cntV;
    int* blkSum = isE ? g_blkSumE : g_blkSumV;

    int i4 = lb * 1024 + threadIdx.x;          // int4 index
    int s = 0;
    if (i4 * 4 < n) {                           // n % 4 == 0 for both arrays
        int4 c = ((const int4*)cnt)[i4];
        s = c.x + c.y + c.z + c.w;
    }
    // block reduce
    __shared__ int ws[32];
    int lane = threadIdx.x & 31, wid = threadIdx.x >> 5;
#pragma unroll
    for (int o = 16; o > 0; o >>= 1) s += __shfl_xor_sync(0xffffffffu, s, o);
    if (lane == 0) ws[wid] = s;
    __syncthreads();
    if (wid == 0) {
        int t = ws[lane];
#pragma unroll
        for (int o = 16; o > 0; o >>= 1) t += __shfl_xor_sync(0xffffffffu, t, o);
        if (lane == 0) blkSum[lb] = t;
    }
}

// ---------------- scan phase B: scan block sums (1 block, warp per array) ----------------
__global__ void k_scanB() {
    int lane = threadIdx.x & 31, wid = threadIdx.x >> 5;
    if (wid == 0) {
        int v = (lane < NBLK_E) ? g_blkSumE[lane] : 0;
        int incl = v;
#pragma unroll
        for (int o = 1; o < 32; o <<= 1) {
            int t = __shfl_up_sync(0xffffffffu, incl, o);
            if (lane >= o) incl += t;
        }
        if (lane < NBLK_E) g_blkOffE[lane] = incl - v;
        if (lane == 31) g_startE[NM] = incl;
    } else if (wid == 1) {
        int v = (lane < NBLK_V) ? g_blkSumV[lane] : 0;
        int incl = v;
#pragma unroll
        for (int o = 1; o < 32; o <<= 1) {
            int t = __shfl_up_sync(0xffffffffu, incl, o);
            if (lane >= o) incl += t;
        }
        if (lane < NBLK_V) g_blkOffV[lane] = incl - v;
        if (lane == 31) g_startV[NV] = incl;
    }
}

// ---------------- scan phase C: block-local exclusive scan + offset ----------------
__global__ void k_scanC() {
    bool isE = (blockIdx.x < NBLK_E);
    int lb = isE ? blockIdx.x : blockIdx.x - NBLK_E;
    int n = isE ? NM : NV;
    const int* cnt = isE ? g_cntE : g_cntV;
    int* start = isE ? g_startE : g_startV;
    int* cur   = isE ? g_curE : g_curV;
    int blkOff = isE ? g_blkOffE[lb] : g_blkOffV[lb];

    int i4 = lb * 1024 + threadIdx.x;
    int4 c = make_int4(0, 0, 0, 0);
    if (i4 * 4 < n) c = ((const int4*)cnt)[i4];
    int tsum = c.x + c.y + c.z + c.w;

    // block inclusive scan of tsum
    __shared__ int ws[32];
    int lane = threadIdx.x & 31, wid = threadIdx.x >> 5;
    int incl = tsum;
#pragma unroll
    for (int o = 1; o < 32; o <<= 1) {
        int t = __shfl_up_sync(0xffffffffu, incl, o);
        if (lane >= o) incl += t;
    }
    if (lane == 31) ws[wid] = incl;
    __syncthreads();
    if (wid == 0) {
        int w = (lane < 32) ? ws[lane] : 0;
#pragma unroll
        for (int o = 1; o < 32; o <<= 1) {
            int t = __shfl_up_sync(0xffffffffu, w, o);
            if (lane >= o) w += t;
        }
        ws[lane] = w;
    }
    __syncthreads();
    int excl = incl - tsum + (wid > 0 ? ws[wid - 1] : 0) + blkOff;

    if (i4 * 4 < n) {
        int4 st;
        st.x = excl;
        st.y = st.x + c.x;
        st.z = st.y + c.y;
        st.w = st.z + c.z;
        ((int4*)start)[i4] = st;
        ((int4*)cur)[i4]   = st;
    }
}

// ---------------- fill CSR incidence lists ----------------
__global__ void k_fill(const int* __restrict__ vertex, const int* __restrict__ edges) {
    int e = blockIdx.x * blockDim.x + threadIdx.x;
    if (e >= NE) return;
    int v  = __ldg(&vertex[e]);
    int ed = __ldg(&edges[e]);
    int pE = atomicAdd(&g_curE[ed], 1);
    g_incE[pE] = v;
    int pV = atomicAdd(&g_curV[v], 1);
    g_incV[pV] = ed;
}

// ---------------- fp32 GEMM: g_X0 = X @ W (128x128 tile, BK=8) ----------------
__global__ void k_gemm(const float* __restrict__ A, const float* __restrict__ B) {
    __shared__ float As[8][128];
    __shared__ float Bs[8][128];
    const int tid = threadIdx.x;
    const int tx = tid & 15;
    const int ty = tid >> 4;
    const int rowBase = blockIdx.y * 128;
    const int colBase = blockIdx.x * 128;

    const int aRow = tid >> 1;
    const int aK   = (tid & 1) * 4;
    const int bK   = tid >> 5;
    const int bCol = (tid & 31) * 4;

    float acc[8][8];
#pragma unroll
    for (int i = 0; i < 8; i++)
#pragma unroll
        for (int j = 0; j < 8; j++) acc[i][j] = 0.f;

    for (int k0 = 0; k0 < IN_CH; k0 += 8) {
        float4 av = make_float4(0.f, 0.f, 0.f, 0.f);
        int gr = rowBase + aRow;
        if (gr < NV) av = *(const float4*)&A[gr * IN_CH + k0 + aK];
        As[aK + 0][aRow] = av.x;
        As[aK + 1][aRow] = av.y;
        As[aK + 2][aRow] = av.z;
        As[aK + 3][aRow] = av.w;
        float4 bv = *(const float4*)&B[(k0 + bK) * HC + colBase + bCol];
        *(float4*)&Bs[bK][bCol] = bv;
        __syncthreads();

#pragma unroll
        for (int k = 0; k < 8; k++) {
            float a[8], b[8];
            float4 a0 = *(const float4*)&As[k][ty * 8];
            float4 a1 = *(const float4*)&As[k][ty * 8 + 4];
            a[0] = a0.x; a[1] = a0.y; a[2] = a0.z; a[3] = a0.w;
            a[4] = a1.x; a[5] = a1.y; a[6] = a1.z; a[7] = a1.w;
            float4 b0 = *(const float4*)&Bs[k][tx * 8];
            float4 b1 = *(const float4*)&Bs[k][tx * 8 + 4];
            b[0] = b0.x; b[1] = b0.y; b[2] = b0.z; b[3] = b0.w;
            b[4] = b1.x; b[5] = b1.y; b[6] = b1.z; b[7] = b1.w;
#pragma unroll
            for (int i = 0; i < 8; i++)
#pragma unroll
                for (int j = 0; j < 8; j++) acc[i][j] += a[i] * b[j];
        }
        __syncthreads();
    }

#pragma unroll
    for (int i = 0; i < 8; i++) {
        int gr = rowBase + ty * 8 + i;
        if (gr < NV) {
            float* cp = &g_X0[gr * HC + colBase + tx * 8];
            *(float4*)cp       = make_float4(acc[i][0], acc[i][1], acc[i][2], acc[i][3]);
            *(float4*)(cp + 4) = make_float4(acc[i][4], acc[i][5], acc[i][6], acc[i][7]);
        }
    }
}

#define ACC8(A0, A1, X0, X1, W0)                                            \
    A0.x += X0.x * W0; A0.y += X0.y * W0; A0.z += X0.z * W0; A0.w += X0.w * W0; \
    A1.x += X1.x * W0; A1.y += X1.y * W0; A1.z += X1.z * W0; A1.w += X1.w * W0;

// ---------------- per-hyperedge aggregate (mean) + logits (warp per hyperedge) ----------------
__global__ void k_edge_agg(const float* __restrict__ att) {
    int m = (blockIdx.x * blockDim.x + threadIdx.x) >> 5;
    if (m >= NM) return;
    int lane = threadIdx.x & 31;
    int s0 = g_startE[m], s1 = g_startE[m + 1];

    float4 acc0 = make_float4(0.f, 0.f, 0.f, 0.f);
    float4 acc1 = make_float4(0.f, 0.f, 0.f, 0.f);
    int i = s0;
    for (; i + 2 <= s1; i += 2) {
        int v0 = __ldg(&g_incE[i]);
        int v1 = __ldg(&g_incE[i + 1]);
        const float4* xr0 = (const float4*)&g_X0[(size_t)v0 * HC];
        const float4* xr1 = (const float4*)&g_X0[(size_t)v1 * HC];
        float4 xa0 = __ldg(&xr0[lane * 2]), xa1 = __ldg(&xr0[lane * 2 + 1]);
        float4 xb0 = __ldg(&xr1[lane * 2]), xb1 = __ldg(&xr1[lane * 2 + 1]);
        ACC8(acc0, acc1, xa0, xa1, 1.0f);
        ACC8(acc0, acc1, xb0, xb1, 1.0f);
    }
    if (i < s1) {
        int v0 = __ldg(&g_incE[i]);
        const float4* xr0 = (const float4*)&g_X0[(size_t)v0 * HC];
        float4 xa0 = __ldg(&xr0[lane * 2]), xa1 = __ldg(&xr0[lane * 2 + 1]);
        ACC8(acc0, acc1, xa0, xa1, 1.0f);
    }

    float inv = 1.0f / fmaxf((float)(s1 - s0), 1.0f);
    acc0.x *= inv; acc0.y *= inv; acc0.z *= inv; acc0.w *= inv;
    acc1.x *= inv; acc1.y *= inv; acc1.z *= inv; acc1.w *= inv;

    float4* xe = (float4*)&g_Xe[(size_t)m * HC];
    xe[lane * 2]     = acc0;
    xe[lane * 2 + 1] = acc1;

    const float4* at = (const float4*)att;
    float4 b0 = __ldg(&at[lane * 2]), b1 = __ldg(&at[lane * 2 + 1]);
    float p = acc0.x * b0.x + acc0.y * b0.y + acc0.z * b0.z + acc0.w * b0.w
            + acc1.x * b1.x + acc1.y * b1.y + acc1.z * b1.z + acc1.w * b1.w;
    p += __shfl_xor_sync(0xffffffffu, p, 1);
    p += __shfl_xor_sync(0xffffffffu, p, 2);
    if ((lane & 3) == 0) g_alphae[m * NH + (lane >> 2)] = p;
}

__device__ __forceinline__ float gelu1(float x) {
    return 0.5f * x * (1.0f + erff(x * 0.70710678118654752f));
}

// ---------------- fused per-vertex online-softmax + weighted gather + GELU ----------------
__global__ void k_vertex(float* __restrict__ out) {
    int warp = (blockIdx.x * blockDim.x + threadIdx.x) >> 5;
    if (warp >= NV) return;
    int lane = threadIdx.x & 31;

    int s0 = g_startV[warp], s1 = g_startV[warp + 1];
    int deg = s1 - s0;

    int h = lane & 7, islot = lane >> 3;

    // online (max, sum) over this lane's subset for head h
    float m = -INFINITY, s = 0.f;
    for (int i = islot; i < deg; i += 4) {
        int ed = __ldg(&g_incV[s0 + i]);
        float a = g_alphae[ed * NH + h];
        a = a >= 0.f ? a : 0.2f * a;
        float mn = fmaxf(m, a);
        s = s * __expf(m - mn) + __expf(a - mn);
        m = mn;
    }
    // combine across the 4 subsets per head (xor 8, 16)
#pragma unroll
    for (int off = 8; off <= 16; off <<= 1) {
        float m2 = __shfl_xor_sync(0xffffffffu, m, off);
        float s2 = __shfl_xor_sync(0xffffffffu, s, off);
        float mn = fmaxf(m, m2);
        float sn = 0.f;
        if (s  > 0.f) sn += s  * __expf(m  - mn);
        if (s2 > 0.f) sn += s2 * __expf(m2 - mn);
        m = mn; s = sn;
    }

    // redistribute: lane covers channels [lane*8, lane*8+8), head hh = lane>>2
    int hh = lane >> 2;
    float m_t = __shfl_sync(0xffffffffu, m, hh);
    float s_t = __shfl_sync(0xffffffffu, s, hh);
    float rs = 1.0f / (s_t + 1e-16f);

    float4 acc0 = make_float4(0.f, 0.f, 0.f, 0.f);
    float4 acc1 = make_float4(0.f, 0.f, 0.f, 0.f);
    int i = 0;
    for (; i + 2 <= deg; i += 2) {
        int e0 = __ldg(&g_incV[s0 + i]);
        int e1 = __ldg(&g_incV[s0 + i + 1]);
        float a0 = g_alphae[e0 * NH + hh];
        float a1 = g_alphae[e1 * NH + hh];
        const float4* xr0 = (const float4*)&g_Xe[(size_t)e0 * HC];
        const float4* xr1 = (const float4*)&g_Xe[(size_t)e1 * HC];
        float4 xa0 = __ldg(&xr0[lane * 2]), xa1 = __ldg(&xr0[lane * 2 + 1]);
        float4 xb0 = __ldg(&xr1[lane * 2]), xb1 = __ldg(&xr1[lane * 2 + 1]);
        a0 = a0 >= 0.f ? a0 : 0.2f * a0;
        a1 = a1 >= 0.f ? a1 : 0.2f * a1;
        float w0 = __expf(a0 - m_t) * rs;
        float w1 = __expf(a1 - m_t) * rs;
        ACC8(acc0, acc1, xa0, xa1, w0);
        ACC8(acc0, acc1, xb0, xb1, w1);
    }
    if (i < deg) {
        int e0 = __ldg(&g_incV[s0 + i]);
        float a0 = g_alphae[e0 * NH + hh];
        const float4* xr0 = (const float4*)&g_Xe[(size_t)e0 * HC];
        float4 xa0 = __ldg(&xr0[lane * 2]), xa1 = __ldg(&xr0[lane * 2 + 1]);
        a0 = a0 >= 0.f ? a0 : 0.2f * a0;
        float w0 = __expf(a0 - m_t) * rs;
        ACC8(acc0, acc1, xa0, xa1, w0);
    }

    acc0.x = gelu1(acc0.x); acc0.y = gelu1(acc0.y);
    acc0.z = gelu1(acc0.z); acc0.w = gelu1(acc0.w);
    acc1.x = gelu1(acc1.x); acc1.y = gelu1(acc1.y);
    acc1.z = gelu1(acc1.z); acc1.w = gelu1(acc1.w);

    float4* op = (float4*)&out[(size_t)warp * HC];
    op[lane * 2]     = acc0;
    op[lane * 2 + 1] = acc1;
}

extern "C" void kernel_launch(void* const* d_in, const int* in_sizes, int n_in,
                              void* d_out, int out_size) {
    const float* X      = (const float*)d_in[0];
    const float* W      = (const float*)d_in[1];
    const float* att    = (const float*)d_in[2];
    const int*   vertex = (const int*)d_in[3];
    const int*   edges  = (const int*)d_in[4];
    float* out = (float*)d_out;

    static cudaStream_t s2 = nullptr;
    static cudaEvent_t evFork = nullptr, evJoin = nullptr;
    if (s2 == nullptr) {
        cudaStreamCreate(&s2);
        cudaEventCreateWithFlags(&evFork, cudaEventDisableTiming);
        cudaEventCreateWithFlags(&evJoin, cudaEventDisableTiming);
    }

    // fork: GEMM on side stream, concurrent with CSR build on main stream
    cudaEventRecord(evFork, 0);
    cudaStreamWaitEvent(s2, evFork, 0);
    {
        dim3 grid(HC / 128, (NV + 127) / 128);
        k_gemm<<<grid, 256, 0, s2>>>(X, W);
    }
    k_init<<<(NM + 255) / 256, 256>>>();
    k_hist<<<(NE + 255) / 256, 256>>>(vertex, edges);
    k_scanA<<<NBLK_E + NBLK_V, 1024>>>();
    k_scanB<<<1, 64>>>();
    k_scanC<<<NBLK_E + NBLK_V, 1024>>>();
    k_fill<<<(NE + 255) / 256, 256>>>(vertex, edges);
    // join: edge aggregation needs both X0 (s2) and CSR (main)
    cudaEventRecord(evJoin, s2);
    cudaStreamWaitEvent(0, evJoin, 0);

    k_edge_agg<<<(NM * 32 + 255) / 256, 256>>>(att);
    k_vertex<<<(NV * 32 + 255) / 256, 256>>>(out);
}

// round 6
// speedup vs baseline: 4.3033x; 1.2890x over previous
#include <cuda_runtime.h>
#include <cuda_bf16.h>
#include <math.h>

#define NV 50000
#define NE 600000
#define NM 100000
#define IN_CH 256
#define HC 256
#define NH 8

#define SCAN_CHUNK 4096
#define NBLK_E ((NM + SCAN_CHUNK - 1) / SCAN_CHUNK)   // 25
#define NBLK_V ((NV + SCAN_CHUNK - 1) / SCAN_CHUNK)   // 13

// ---------------- scratch (device globals) ----------------
__device__ float g_X0[NV * HC];        // X @ W
__device__ float g_Xe[NM * HC];        // hyperedge feature MEANS
__device__ float g_alphae[NM * NH];    // per-hyperedge logits
__device__ int   g_cntE[NM], g_cntV[NV];
__device__ int   g_startE[NM + 1], g_startV[NV + 1];
__device__ int   g_curE[NM], g_curV[NV];
__device__ int   g_incE[NE];
__device__ int   g_incV[NE];
__device__ int   g_blkSumE[NBLK_E], g_blkSumV[NBLK_V];
__device__ int   g_blkOffE[NBLK_E], g_blkOffV[NBLK_V];
// W split into bf16 hi/lo, transposed to [n][k-pair] packed bf16x2
__device__ unsigned g_Wt_hi[HC * (IN_CH / 2)];
__device__ unsigned g_Wt_lo[HC * (IN_CH / 2)];

// ---------------- split helper: two floats -> packed bf16x2 hi + lo ----------------
__device__ __forceinline__ void split2(float x, float y, unsigned& h, unsigned& l) {
    __nv_bfloat16 hx = __float2bfloat16_rn(x);
    __nv_bfloat16 hy = __float2bfloat16_rn(y);
    float lxf = x - __bfloat162float(hx);
    float lyf = y - __bfloat162float(hy);
    __nv_bfloat16 lx = __float2bfloat16_rn(lxf);
    __nv_bfloat16 ly = __float2bfloat16_rn(lyf);
    h = ((unsigned)__bfloat16_as_ushort(hy) << 16) | (unsigned)__bfloat16_as_ushort(hx);
    l = ((unsigned)__bfloat16_as_ushort(ly) << 16) | (unsigned)__bfloat16_as_ushort(lx);
}

// ---------------- prep: split + transpose W ----------------
__global__ void k_prepW(const float* __restrict__ W) {
    int idx = blockIdx.x * blockDim.x + threadIdx.x;  // HC * 128
    if (idx >= HC * (IN_CH / 2)) return;
    int n = idx >> 7, p = idx & 127;
    float x = __ldg(&W[(2 * p) * HC + n]);
    float y = __ldg(&W[(2 * p + 1) * HC + n]);
    unsigned h, l;
    split2(x, y, h, l);
    g_Wt_hi[idx] = h;
    g_Wt_lo[idx] = l;
}

#define MMA_BF16(C, A, B)                                                     \
    asm volatile(                                                             \
        "mma.sync.aligned.m16n8k16.row.col.f32.bf16.bf16.f32 "                \
        "{%0,%1,%2,%3}, {%4,%5,%6,%7}, {%8,%9}, {%0,%1,%2,%3};"               \
        : "+f"(C[0]), "+f"(C[1]), "+f"(C[2]), "+f"(C[3])                      \
        : "r"(A[0]), "r"(A[1]), "r"(A[2]), "r"(A[3]), "r"(B[0]), "r"(B[1]))

// ---------------- tensor-core GEMM: g_X0 = X @ W, 3-term split-bf16 ----------------
// 128x128 block tile, BK=32, 8 warps (4 M x 2 N), warp tile 32x64.
__global__ __launch_bounds__(256) void k_gemm(const float* __restrict__ A) {
    __shared__ unsigned As_h[128][17], As_l[128][17];
    __shared__ unsigned Bs_h[128][17], Bs_l[128][17];

    const int tid = threadIdx.x;
    const int wid = tid >> 5, lane = tid & 31;
    const int g = lane >> 2, t = lane & 3;
    const int warpM = wid & 3, warpN = wid >> 2;
    const int rowBase = blockIdx.y * 128;
    const int colBase = blockIdx.x * 128;

    float c[2][8][4];
#pragma unroll
    for (int mt = 0; mt < 2; mt++)
#pragma unroll
        for (int nt = 0; nt < 8; nt++)
#pragma unroll
            for (int r = 0; r < 4; r++) c[mt][nt][r] = 0.f;

    const int lrow = tid >> 1;            // 0..127
    const int lko  = (tid & 1) * 16;      // float offset within BK=32
    const int lpo  = (tid & 1) * 8;       // pair offset (8 pairs)
    const bool aval = (rowBase + lrow) < NV;
    const float* aBase = A + (size_t)(rowBase + lrow) * IN_CH + lko;
    const int bn = tid >> 1;              // B n-row 0..127

    for (int k0 = 0; k0 < IN_CH; k0 += 32) {
        // stage A (convert fp32 -> bf16 hi/lo)
#pragma unroll
        for (int j = 0; j < 4; j++) {
            float4 v = make_float4(0.f, 0.f, 0.f, 0.f);
            if (aval) v = *(const float4*)(aBase + k0 + j * 4);
            unsigned h0, l0, h1, l1;
            split2(v.x, v.y, h0, l0);
            split2(v.z, v.w, h1, l1);
            As_h[lrow][lpo + j * 2]     = h0;
            As_h[lrow][lpo + j * 2 + 1] = h1;
            As_l[lrow][lpo + j * 2]     = l0;
            As_l[lrow][lpo + j * 2 + 1] = l1;
        }
        // stage B (pre-split, coalesced uint4)
        {
            int p0 = k0 >> 1;
            const unsigned* src_h = &g_Wt_hi[(size_t)(colBase + bn) * 128 + p0 + lpo];
            const unsigned* src_l = &g_Wt_lo[(size_t)(colBase + bn) * 128 + p0 + lpo];
            uint4 h0 = ((const uint4*)src_h)[0];
            uint4 h1 = ((const uint4*)src_h)[1];
            uint4 l0 = ((const uint4*)src_l)[0];
            uint4 l1 = ((const uint4*)src_l)[1];
            Bs_h[bn][lpo + 0] = h0.x; Bs_h[bn][lpo + 1] = h0.y;
            Bs_h[bn][lpo + 2] = h0.z; Bs_h[bn][lpo + 3] = h0.w;
            Bs_h[bn][lpo + 4] = h1.x; Bs_h[bn][lpo + 5] = h1.y;
            Bs_h[bn][lpo + 6] = h1.z; Bs_h[bn][lpo + 7] = h1.w;
            Bs_l[bn][lpo + 0] = l0.x; Bs_l[bn][lpo + 1] = l0.y;
            Bs_l[bn][lpo + 2] = l0.z; Bs_l[bn][lpo + 3] = l0.w;
            Bs_l[bn][lpo + 4] = l1.x; Bs_l[bn][lpo + 5] = l1.y;
            Bs_l[bn][lpo + 6] = l1.z; Bs_l[bn][lpo + 7] = l1.w;
        }
        __syncthreads();

#pragma unroll
        for (int s = 0; s < 2; s++) {
            const int pb = s * 8;
            unsigned ah[2][4], al[2][4];
#pragma unroll
            for (int mt = 0; mt < 2; mt++) {
                int r = warpM * 32 + mt * 16;
                ah[mt][0] = As_h[r + g][pb + t];
                ah[mt][1] = As_h[r + g + 8][pb + t];
                ah[mt][2] = As_h[r + g][pb + t + 4];
                ah[mt][3] = As_h[r + g + 8][pb + t + 4];
                al[mt][0] = As_l[r + g][pb + t];
                al[mt][1] = As_l[r + g + 8][pb + t];
                al[mt][2] = As_l[r + g][pb + t + 4];
                al[mt][3] = As_l[r + g + 8][pb + t + 4];
            }
            unsigned bh[8][2], bl[8][2];
#pragma unroll
            for (int nt = 0; nt < 8; nt++) {
                int n = warpN * 64 + nt * 8 + g;
                bh[nt][0] = Bs_h[n][pb + t];
                bh[nt][1] = Bs_h[n][pb + t + 4];
                bl[nt][0] = Bs_l[n][pb + t];
                bl[nt][1] = Bs_l[n][pb + t + 4];
            }
#pragma unroll
            for (int mt = 0; mt < 2; mt++)
#pragma unroll
                for (int nt = 0; nt < 8; nt++) {
                    MMA_BF16(c[mt][nt], ah[mt], bh[nt]);
                    MMA_BF16(c[mt][nt], ah[mt], bl[nt]);
                    MMA_BF16(c[mt][nt], al[mt], bh[nt]);
                }
        }
        __syncthreads();
    }

    // epilogue
#pragma unroll
    for (int mt = 0; mt < 2; mt++) {
        int r0 = rowBase + warpM * 32 + mt * 16 + g;
#pragma unroll
        for (int nt = 0; nt < 8; nt++) {
            int cc = colBase + warpN * 64 + nt * 8 + 2 * t;
            if (r0 < NV)
                *(float2*)&g_X0[(size_t)r0 * HC + cc] = make_float2(c[mt][nt][0], c[mt][nt][1]);
            if (r0 + 8 < NV)
                *(float2*)&g_X0[(size_t)(r0 + 8) * HC + cc] = make_float2(c[mt][nt][2], c[mt][nt][3]);
        }
    }
}

// ---------------- init: zero histograms ----------------
__global__ void k_init() {
    int i = blockIdx.x * blockDim.x + threadIdx.x;
    if (i < NM) g_cntE[i] = 0;
    if (i < NV) g_cntV[i] = 0;
}

// ---------------- histogram ----------------
__global__ void k_hist(const int* __restrict__ vertex, const int* __restrict__ edges) {
    int e = blockIdx.x * blockDim.x + threadIdx.x;
    if (e >= NE) return;
    atomicAdd(&g_cntE[__ldg(&edges[e])], 1);
    atomicAdd(&g_cntV[__ldg(&vertex[e])], 1);
}

// ---------------- scan phase A ----------------
__global__ void k_scanA() {
    bool isE = (blockIdx.x < NBLK_E);
    int lb = isE ? blockIdx.x : blockIdx.x - NBLK_E;
    int n = isE ? NM : NV;
    const int* cnt = isE ? g_cntE : g_cntV;
    int* blkSum = isE ? g_blkSumE : g_blkSumV;

    int i4 = lb * 1024 + threadIdx.x;
    int s = 0;
    if (i4 * 4 < n) {
        int4 c = ((const int4*)cnt)[i4];
        s = c.x + c.y + c.z + c.w;
    }
    __shared__ int ws[32];
    int lane = threadIdx.x & 31, wid = threadIdx.x >> 5;
#pragma unroll
    for (int o = 16; o > 0; o >>= 1) s += __shfl_xor_sync(0xffffffffu, s, o);
    if (lane == 0) ws[wid] = s;
    __syncthreads();
    if (wid == 0) {
        int tv = ws[lane];
#pragma unroll
        for (int o = 16; o > 0; o >>= 1) tv += __shfl_xor_sync(0xffffffffu, tv, o);
        if (lane == 0) blkSum[lb] = tv;
    }
}

// ---------------- scan phase B ----------------
__global__ void k_scanB() {
    int lane = threadIdx.x & 31, wid = threadIdx.x >> 5;
    if (wid == 0) {
        int v = (lane < NBLK_E) ? g_blkSumE[lane] : 0;
        int incl = v;
#pragma unroll
        for (int o = 1; o < 32; o <<= 1) {
            int t = __shfl_up_sync(0xffffffffu, incl, o);
            if (lane >= o) incl += t;
        }
        if (lane < NBLK_E) g_blkOffE[lane] = incl - v;
        if (lane == 31) g_startE[NM] = incl;
    } else if (wid == 1) {
        int v = (lane < NBLK_V) ? g_blkSumV[lane] : 0;
        int incl = v;
#pragma unroll
        for (int o = 1; o < 32; o <<= 1) {
            int t = __shfl_up_sync(0xffffffffu, incl, o);
            if (lane >= o) incl += t;
        }
        if (lane < NBLK_V) g_blkOffV[lane] = incl - v;
        if (lane == 31) g_startV[NV] = incl;
    }
}

// ---------------- scan phase C ----------------
__global__ void k_scanC() {
    bool isE = (blockIdx.x < NBLK_E);
    int lb = isE ? blockIdx.x : blockIdx.x - NBLK_E;
    int n = isE ? NM : NV;
    const int* cnt = isE ? g_cntE : g_cntV;
    int* start = isE ? g_startE : g_startV;
    int* cur   = isE ? g_curE : g_curV;
    int blkOff = isE ? g_blkOffE[lb] : g_blkOffV[lb];

    int i4 = lb * 1024 + threadIdx.x;
    int4 c = make_int4(0, 0, 0, 0);
    if (i4 * 4 < n) c = ((const int4*)cnt)[i4];
    int tsum = c.x + c.y + c.z + c.w;

    __shared__ int ws[32];
    int lane = threadIdx.x & 31, wid = threadIdx.x >> 5;
    int incl = tsum;
#pragma unroll
    for (int o = 1; o < 32; o <<= 1) {
        int t = __shfl_up_sync(0xffffffffu, incl, o);
        if (lane >= o) incl += t;
    }
    if (lane == 31) ws[wid] = incl;
    __syncthreads();
    if (wid == 0) {
        int w = ws[lane];
#pragma unroll
        for (int o = 1; o < 32; o <<= 1) {
            int t = __shfl_up_sync(0xffffffffu, w, o);
            if (lane >= o) w += t;
        }
        ws[lane] = w;
    }
    __syncthreads();
    int excl = incl - tsum + (wid > 0 ? ws[wid - 1] : 0) + blkOff;

    if (i4 * 4 < n) {
        int4 st;
        st.x = excl;
        st.y = st.x + c.x;
        st.z = st.y + c.y;
        st.w = st.z + c.z;
        ((int4*)start)[i4] = st;
        ((int4*)cur)[i4]   = st;
    }
}

// ---------------- fill CSR incidence lists ----------------
__global__ void k_fill(const int* __restrict__ vertex, const int* __restrict__ edges) {
    int e = blockIdx.x * blockDim.x + threadIdx.x;
    if (e >= NE) return;
    int v  = __ldg(&vertex[e]);
    int ed = __ldg(&edges[e]);
    int pE = atomicAdd(&g_curE[ed], 1);
    g_incE[pE] = v;
    int pV = atomicAdd(&g_curV[v], 1);
    g_incV[pV] = ed;
}

#define ACC8(A0, A1, X0, X1, W0)                                            \
    A0.x += X0.x * W0; A0.y += X0.y * W0; A0.z += X0.z * W0; A0.w += X0.w * W0; \
    A1.x += X1.x * W0; A1.y += X1.y * W0; A1.z += X1.z * W0; A1.w += X1.w * W0;

// ---------------- per-hyperedge aggregate (mean) + logits ----------------
__global__ void k_edge_agg(const float* __restrict__ att) {
    int m = (blockIdx.x * blockDim.x + threadIdx.x) >> 5;
    if (m >= NM) return;
    int lane = threadIdx.x & 31;
    int s0 = g_startE[m], s1 = g_startE[m + 1];

    float4 acc0 = make_float4(0.f, 0.f, 0.f, 0.f);
    float4 acc1 = make_float4(0.f, 0.f, 0.f, 0.f);
    int i = s0;
    for (; i + 2 <= s1; i += 2) {
        int v0 = __ldg(&g_incE[i]);
        int v1 = __ldg(&g_incE[i + 1]);
        const float4* xr0 = (const float4*)&g_X0[(size_t)v0 * HC];
        const float4* xr1 = (const float4*)&g_X0[(size_t)v1 * HC];
        float4 xa0 = __ldg(&xr0[lane * 2]), xa1 = __ldg(&xr0[lane * 2 + 1]);
        float4 xb0 = __ldg(&xr1[lane * 2]), xb1 = __ldg(&xr1[lane * 2 + 1]);
        ACC8(acc0, acc1, xa0, xa1, 1.0f);
        ACC8(acc0, acc1, xb0, xb1, 1.0f);
    }
    if (i < s1) {
        int v0 = __ldg(&g_incE[i]);
        const float4* xr0 = (const float4*)&g_X0[(size_t)v0 * HC];
        float4 xa0 = __ldg(&xr0[lane * 2]), xa1 = __ldg(&xr0[lane * 2 + 1]);
        ACC8(acc0, acc1, xa0, xa1, 1.0f);
    }

    float inv = 1.0f / fmaxf((float)(s1 - s0), 1.0f);
    acc0.x *= inv; acc0.y *= inv; acc0.z *= inv; acc0.w *= inv;
    acc1.x *= inv; acc1.y *= inv; acc1.z *= inv; acc1.w *= inv;

    float4* xe = (float4*)&g_Xe[(size_t)m * HC];
    xe[lane * 2]     = acc0;
    xe[lane * 2 + 1] = acc1;

    const float4* at = (const float4*)att;
    float4 b0 = __ldg(&at[lane * 2]), b1 = __ldg(&at[lane * 2 + 1]);
    float p = acc0.x * b0.x + acc0.y * b0.y + acc0.z * b0.z + acc0.w * b0.w
            + acc1.x * b1.x + acc1.y * b1.y + acc1.z * b1.z + acc1.w * b1.w;
    p += __shfl_xor_sync(0xffffffffu, p, 1);
    p += __shfl_xor_sync(0xffffffffu, p, 2);
    if ((lane & 3) == 0) g_alphae[m * NH + (lane >> 2)] = p;
}

__device__ __forceinline__ float gelu1(float x) {
    return 0.5f * x * (1.0f + erff(x * 0.70710678118654752f));
}

// ---------------- fused per-vertex online-softmax + weighted gather + GELU ----------------
__global__ void k_vertex(float* __restrict__ out) {
    int warp = (blockIdx.x * blockDim.x + threadIdx.x) >> 5;
    if (warp >= NV) return;
    int lane = threadIdx.x & 31;

    int s0 = g_startV[warp], s1 = g_startV[warp + 1];
    int deg = s1 - s0;

    int h = lane & 7, islot = lane >> 3;

    float m = -INFINITY, s = 0.f;
    for (int i = islot; i < deg; i += 4) {
        int ed = __ldg(&g_incV[s0 + i]);
        float a = g_alphae[ed * NH + h];
        a = a >= 0.f ? a : 0.2f * a;
        float mn = fmaxf(m, a);
        s = s * __expf(m - mn) + __expf(a - mn);
        m = mn;
    }
#pragma unroll
    for (int off = 8; off <= 16; off <<= 1) {
        float m2 = __shfl_xor_sync(0xffffffffu, m, off);
        float s2 = __shfl_xor_sync(0xffffffffu, s, off);
        float mn = fmaxf(m, m2);
        float sn = 0.f;
        if (s  > 0.f) sn += s  * __expf(m  - mn);
        if (s2 > 0.f) sn += s2 * __expf(m2 - mn);
        m = mn; s = sn;
    }

    int hh = lane >> 2;
    float m_t = __shfl_sync(0xffffffffu, m, hh);
    float s_t = __shfl_sync(0xffffffffu, s, hh);
    float rs = 1.0f / (s_t + 1e-16f);

    float4 acc0 = make_float4(0.f, 0.f, 0.f, 0.f);
    float4 acc1 = make_float4(0.f, 0.f, 0.f, 0.f);
    int i = 0;
    for (; i + 2 <= deg; i += 2) {
        int e0 = __ldg(&g_incV[s0 + i]);
        int e1 = __ldg(&g_incV[s0 + i + 1]);
        float a0 = g_alphae[e0 * NH + hh];
        float a1 = g_alphae[e1 * NH + hh];
        const float4* xr0 = (const float4*)&g_Xe[(size_t)e0 * HC];
        const float4* xr1 = (const float4*)&g_Xe[(size_t)e1 * HC];
        float4 xa0 = __ldg(&xr0[lane * 2]), xa1 = __ldg(&xr0[lane * 2 + 1]);
        float4 xb0 = __ldg(&xr1[lane * 2]), xb1 = __ldg(&xr1[lane * 2 + 1]);
        a0 = a0 >= 0.f ? a0 : 0.2f * a0;
        a1 = a1 >= 0.f ? a1 : 0.2f * a1;
        float w0 = __expf(a0 - m_t) * rs;
        float w1 = __expf(a1 - m_t) * rs;
        ACC8(acc0, acc1, xa0, xa1, w0);
        ACC8(acc0, acc1, xb0, xb1, w1);
    }
    if (i < deg) {
        int e0 = __ldg(&g_incV[s0 + i]);
        float a0 = g_alphae[e0 * NH + hh];
        const float4* xr0 = (const float4*)&g_Xe[(size_t)e0 * HC];
        float4 xa0 = __ldg(&xr0[lane * 2]), xa1 = __ldg(&xr0[lane * 2 + 1]);
        a0 = a0 >= 0.f ? a0 : 0.2f * a0;
        float w0 = __expf(a0 - m_t) * rs;
        ACC8(acc0, acc1, xa0, xa1, w0);
    }

    acc0.x = gelu1(acc0.x); acc0.y = gelu1(acc0.y);
    acc0.z = gelu1(acc0.z); acc0.w = gelu1(acc0.w);
    acc1.x = gelu1(acc1.x); acc1.y = gelu1(acc1.y);
    acc1.z = gelu1(acc1.z); acc1.w = gelu1(acc1.w);

    float4* op = (float4*)&out[(size_t)warp * HC];
    op[lane * 2]     = acc0;
    op[lane * 2 + 1] = acc1;
}

extern "C" void kernel_launch(void* const* d_in, const int* in_sizes, int n_in,
                              void* d_out, int out_size) {
    const float* X      = (const float*)d_in[0];
    const float* W      = (const float*)d_in[1];
    const float* att    = (const float*)d_in[2];
    const int*   vertex = (const int*)d_in[3];
    const int*   edges  = (const int*)d_in[4];
    float* out = (float*)d_out;

    static cudaStream_t s2 = nullptr;
    static cudaEvent_t evFork = nullptr, evJoin = nullptr;
    if (s2 == nullptr) {
        cudaStreamCreate(&s2);
        cudaEventCreateWithFlags(&evFork, cudaEventDisableTiming);
        cudaEventCreateWithFlags(&evJoin, cudaEventDisableTiming);
    }

    // fork: GEMM (tensor core) on side stream, concurrent with CSR build
    cudaEventRecord(evFork, 0);
    cudaStreamWaitEvent(s2, evFork, 0);
    k_prepW<<<(HC * (IN_CH / 2) + 255) / 256, 256, 0, s2>>>(W);
    {
        dim3 grid(HC / 128, (NV + 127) / 128);
        k_gemm<<<grid, 256, 0, s2>>>(X);
    }
    k_init<<<(NM + 255) / 256, 256>>>();
    k_hist<<<(NE + 255) / 256, 256>>>(vertex, edges);
    k_scanA<<<NBLK_E + NBLK_V, 1024>>>();
    k_scanB<<<1, 64>>>();
    k_scanC<<<NBLK_E + NBLK_V, 1024>>>();
    k_fill<<<(NE + 255) / 256, 256>>>(vertex, edges);
    // join: edge aggregation needs both X0 (s2) and CSR (main)
    cudaEventRecord(evJoin, s2);
    cudaStreamWaitEvent(0, evJoin, 0);

    k_edge_agg<<<(NM * 32 + 255) / 256, 256>>>(att);
    k_vertex<<<(NV * 32 + 255) / 256, 256>>>(out);
}